// round 4
// baseline (speedup 1.0000x reference)
#include <cuda_runtime.h>

// Problem constants
#define B_  8
#define H_  256
#define W_  256
#define P_  8
#define PH_ 32
#define N_  1024   // PH*PH
#define S_  64     // P*P
#define T_  64
#define INV_TEMP 10.0f
#define LN_EPS 1e-5f

// One CTA = one horizontally-adjacent patch PAIR (n0 = 2k, n1 = 2k+1).
__global__ __launch_bounds__(256, 6)
void scs_kernel(const float* __restrict__ spikes,
                const float* __restrict__ Wd,
                const float* __restrict__ gamma,
                const float* __restrict__ beta,
                const float* __restrict__ gates,
                const float* __restrict__ biases,
                float* __restrict__ out) {
    __shared__ float s_patch[128];   // [patch g][64] row-major pixels
    __shared__ float s_out[128];     // [patch g][64] matvec results

    const int blk   = blockIdx.x;        // 0..4095
    const int b     = blk >> 9;          // 512 pairs per batch
    const int npair = blk & 511;
    const int n0    = npair << 1;        // even patch index
    const int py    = n0 >> 5;
    const int px    = n0 & 31;           // even
    const int tid   = threadIdx.x;

    const size_t tile0 = ((size_t)(b * N_ + n0)) << 12;   // floats

    // ---- front-issue patch0's W loads (warp-contiguous 512B per instr) ----
    const float4* Wp0 = (const float4*)(Wd + tile0);
    float4 w0 = __ldcs(Wp0 + tid);
    float4 w1 = __ldcs(Wp0 + tid + 256);
    float4 w2 = __ldcs(Wp0 + tid + 512);
    float4 w3 = __ldcs(Wp0 + tid + 768);

    // ---- load BOTH patches' pixels (adjacent: 8 rows x 16 floats contiguous) ----
    if (tid < 128) {
        const int r = tid >> 4, c = tid & 15;
        const float v = spikes[((size_t)b << 16) + ((py << 3) + r) * 256 + (px << 3) + c];
        s_patch[((c >> 3) << 6) + (r << 3) + (c & 7)] = v;
    }
    __syncthreads();   // bar1: patches ready

    const int jp = tid & 15;
    const int r0 = tid >> 4;   // 0..15

    // ================= matvec patch 0 =================
    {
        const float4 p = ((const float4*)s_patch)[jp];
        float a0 = w0.x * p.x + w0.y * p.y + w0.z * p.z + w0.w * p.w;
        float a1 = w1.x * p.x + w1.y * p.y + w1.z * p.z + w1.w * p.w;
        float a2 = w2.x * p.x + w2.y * p.y + w2.z * p.z + w2.w * p.w;
        float a3 = w3.x * p.x + w3.y * p.y + w3.z * p.z + w3.w * p.w;

        // w regs dead -> issue patch1's W loads NOW (overlap the shuffle chain)
        const float4* Wp1 = (const float4*)(Wd + tile0 + 4096);
        w0 = __ldcs(Wp1 + tid);
        w1 = __ldcs(Wp1 + tid + 256);
        w2 = __ldcs(Wp1 + tid + 512);
        w3 = __ldcs(Wp1 + tid + 768);

#pragma unroll
        for (int o = 1; o < 16; o <<= 1) {
            a0 += __shfl_xor_sync(0xffffffffu, a0, o);
            a1 += __shfl_xor_sync(0xffffffffu, a1, o);
            a2 += __shfl_xor_sync(0xffffffffu, a2, o);
            a3 += __shfl_xor_sync(0xffffffffu, a3, o);
        }
        if (jp == 0) {
            s_out[r0]      = a0;
            s_out[r0 + 16] = a1;
            s_out[r0 + 32] = a2;
            s_out[r0 + 48] = a3;
        }
    }

    // ================= matvec patch 1 =================
    {
        const float4 p = ((const float4*)(s_patch + 64))[jp];
        float a0 = w0.x * p.x + w0.y * p.y + w0.z * p.z + w0.w * p.w;
        float a1 = w1.x * p.x + w1.y * p.y + w1.z * p.z + w1.w * p.w;
        float a2 = w2.x * p.x + w2.y * p.y + w2.z * p.z + w2.w * p.w;
        float a3 = w3.x * p.x + w3.y * p.y + w3.z * p.z + w3.w * p.w;
#pragma unroll
        for (int o = 1; o < 16; o <<= 1) {
            a0 += __shfl_xor_sync(0xffffffffu, a0, o);
            a1 += __shfl_xor_sync(0xffffffffu, a1, o);
            a2 += __shfl_xor_sync(0xffffffffu, a2, o);
            a3 += __shfl_xor_sync(0xffffffffu, a3, o);
        }
        if (jp == 0) {
            s_out[64 + r0]      = a0;
            s_out[64 + r0 + 16] = a1;
            s_out[64 + r0 + 32] = a2;
            s_out[64 + r0 + 48] = a3;
        }
    }
    __syncthreads();   // bar2: both s_out sets ready

    // ---- warps 0,1: parallel epilogues (LN + softmax + affine), direct store ----
    if (tid < 64) {
        const int g    = tid >> 5;       // patch within pair
        const int l    = tid & 31;
        const int base = g << 6;
        const int n    = n0 + g;

        const float v0 = s_out[base + l];
        const float v1 = s_out[base + l + 32];
        const float q0 = s_patch[base + l];
        const float q1 = s_patch[base + l + 32];

        float ps = q0 + q1;
        float sm = v0 + v1;
#pragma unroll
        for (int o = 16; o > 0; o >>= 1) {
            ps += __shfl_xor_sync(0xffffffffu, ps, o);
            sm += __shfl_xor_sync(0xffffffffu, sm, o);
        }
        const float mu = sm * (1.0f / 64.0f);
        const float d0 = v0 - mu, d1 = v1 - mu;
        float sq = d0 * d0 + d1 * d1;
#pragma unroll
        for (int o = 16; o > 0; o >>= 1)
            sq += __shfl_xor_sync(0xffffffffu, sq, o);
        const float rstd = rsqrtf(sq * (1.0f / 64.0f) + LN_EPS);

        const float z0 = (d0 * rstd * __ldg(&gamma[l])      + __ldg(&beta[l]))      * INV_TEMP;
        const float z1 = (d1 * rstd * __ldg(&gamma[l + 32]) + __ldg(&beta[l + 32])) * INV_TEMP;

        float mx = fmaxf(z0, z1);
#pragma unroll
        for (int o = 16; o > 0; o >>= 1)
            mx = fmaxf(mx, __shfl_xor_sync(0xffffffffu, mx, o));

        const float e0 = __expf(z0 - mx);
        const float e1 = __expf(z1 - mx);
        float se = e0 + e1;
#pragma unroll
        for (int o = 16; o > 0; o >>= 1)
            se += __shfl_xor_sync(0xffffffffu, se, o);

        const float affine = __ldg(&gates[n]) * ps + __ldg(&biases[n]);
        const float scale  = affine / se;

        // direct fold-store: pixel t -> (row py*8 + t/8, col (px+g)*8 + t%8)
        const size_t ob = ((size_t)b << 16) + ((px + g) << 3);
        out[ob + ((py << 3) + (l >> 3)) * 256 + (l & 7)]            = e0 * scale;
        const int l2 = l + 32;
        out[ob + ((py << 3) + (l2 >> 3)) * 256 + (l2 & 7)]          = e1 * scale;
    }
}

extern "C" void kernel_launch(void* const* d_in, const int* in_sizes, int n_in,
                              void* d_out, int out_size) {
    const float* spikes = (const float*)d_in[0];
    const float* Wd     = (const float*)d_in[1];
    const float* gamma  = (const float*)d_in[2];
    const float* beta   = (const float*)d_in[3];
    const float* gates  = (const float*)d_in[4];
    const float* biases = (const float*)d_in[5];
    float* out = (float*)d_out;

    scs_kernel<<<(B_ * N_) / 2, 256>>>(spikes, Wd, gamma, beta, gates, biases, out);
}